// round 4
// baseline (speedup 1.0000x reference)
#include <cuda_runtime.h>
#include <math.h>

// ---------------- problem constants ----------------
#define TSZ    480000
#define BATCH  8
#define CHUNK  4096
#define STRIDE 3072
#define NCH    157
#define NF     13
#define NFFT   1024
#define HOP    256
#define FBINS  513
#define HDIM   256
#define EDIM   128
#define N3H    768
#define SEQ    (BATCH*NCH)   // 1256
#define ROWS   (SEQ*NF)      // 16328
#define CPB    (NCH*NF)      // 2041 frames per batch
#define KPAD   528           // FBINS padded (mult of 16)
#define PWLD   1152          // proj_w padded cols (9*128)
#define NGB    1026          // 2*FBINS
#define PI_F   3.14159265358979323846f

// ---------------- scratch ----------------
__device__ float g_magp[ROWS*KPAD];
__device__ float g_cosp[ROWS*FBINS];
__device__ float g_sinp[ROWS*FBINS];
__device__ float g_xg  [ROWS*N3H];
__device__ float g_hs  [ROWS*HDIM];
__device__ float g_gb  [ROWS*NGB];
__device__ float g_y   [ROWS*NFFT];
__device__ float g_embrow[BATCH*N3H];
__device__ float g_wsum[CHUNK];
__device__ float g_wxp [KPAD*N3H];
__device__ float g_pwp [HDIM*PWLD];
__device__ float g_twr[512], g_twi[512];
__device__ float g_win[NFFT];

__device__ __forceinline__ float sigf(float x) { return 1.f/(1.f + expf(-x)); }

__device__ __forceinline__ unsigned f2tf32(float x) {
    unsigned r; asm("cvt.rna.tf32.f32 %0, %1;" : "=r"(r) : "f"(x)); return r;
}
__device__ __forceinline__ void mma8(float* c, const unsigned* a, unsigned b0, unsigned b1) {
    asm volatile("mma.sync.aligned.m16n8k8.row.col.f32.tf32.tf32.f32 "
        "{%0,%1,%2,%3}, {%4,%5,%6,%7}, {%8,%9}, {%0,%1,%2,%3};\n"
        : "+f"(c[0]), "+f"(c[1]), "+f"(c[2]), "+f"(c[3])
        : "r"(a[0]), "r"(a[1]), "r"(a[2]), "r"(a[3]), "r"(b0), "r"(b1));
}

// ---------------- tables: twiddles, window, wsum ----------------
__global__ void k_tables() {
    int i = blockIdx.x*blockDim.x + threadIdx.x;
    if (i < 512) {
        float s, c; sincosf(-(2.f*PI_F/NFFT)*i, &s, &c);
        g_twr[i] = c; g_twi[i] = s;
    }
    if (i < NFFT)
        g_win[i] = 0.5f - 0.5f*cosf((2.f*PI_F/NFFT)*i);
    if (i < CHUNK) {
        float ws = 0.f;
        for (int fi = 0; fi < NF; fi++) {
            int d = i - fi*HOP;
            if (d >= 0 && d < NFFT) {
                float w = 0.5f - 0.5f*cosf((2.f*PI_F/NFFT)*d);
                ws += w*w;
            }
        }
        g_wsum[i] = ws;
    }
}

// ---------------- merged prep: pad wx, pad pw, embrow ----------------
#define NBWX ((KPAD*N3H)/256)    // 1584
#define NBPW ((HDIM*PWLD)/256)   // 1152
__global__ void k_prep(const float* __restrict__ wx,
                       const float* __restrict__ pw,
                       const float* __restrict__ emb_table,
                       const int*   __restrict__ effect_id) {
    __shared__ float se[EDIM];
    const int bx = blockIdx.x, tid = threadIdx.x;
    if (bx < NBWX) {
        int i = bx*256 + tid;
        int k = i / N3H, n = i % N3H;
        g_wxp[i] = (k < FBINS) ? wx[k*N3H + n] : 0.f;
    } else if (bx < NBWX + NBPW) {
        int i = (bx - NBWX)*256 + tid;
        int k = i / PWLD, n = i % PWLD;
        g_pwp[i] = (n < NGB) ? pw[k*NGB + n] : 0.f;
    } else {
        int b = bx - NBWX - NBPW;   // 0..7
        if (tid < EDIM) se[tid] = emb_table[effect_id[b]*EDIM + tid];
        __syncthreads();
        for (int j = tid; j < N3H; j += 256) {
            float acc = 0.f;
            #pragma unroll 8
            for (int k = 0; k < EDIM; k++)
                acc += se[k] * wx[(FBINS + k)*N3H + j];
            g_embrow[b*N3H + j] = acc;
        }
    }
}

// ---------------- forward STFT ----------------
__global__ void k_fwdfft(const float* __restrict__ audio) {
    __shared__ float sr[NFFT], si[NFFT];
    __shared__ float twr[512], twi[512];
    const int fr  = blockIdx.x;
    const int tid = threadIdx.x;
    const int b   = fr / CPB;
    const int rem = fr % CPB;
    const int base = (rem/NF)*STRIDE + (rem%NF)*HOP;

    for (int k = tid; k < 512; k += 256) { twr[k] = g_twr[k]; twi[k] = g_twi[k]; }
    for (int n = tid; n < NFFT; n += 256) {
        int s = base + n;
        float v = (s < TSZ) ? audio[b*TSZ + s] : 0.f;
        int j = __brev((unsigned)n) >> 22;
        sr[j] = v*g_win[n]; si[j] = 0.f;
    }
    __syncthreads();
    for (int s = 1; s <= 10; s++) {
        int half = 1 << (s-1);
        for (int t = tid; t < 512; t += 256) {
            int pos = t & (half-1);
            int grp = t >> (s-1);
            int i1 = (grp << s) + pos;
            int i2 = i1 + half;
            int ti_ = pos << (10 - s);
            float wr = twr[ti_], wi = twi[ti_];
            float xr = sr[i2], xi = si[i2];
            float tr = wr*xr - wi*xi;
            float tq = wr*xi + wi*xr;
            sr[i2] = sr[i1] - tr; si[i2] = si[i1] - tq;
            sr[i1] += tr;         si[i1] += tq;
        }
        __syncthreads();
    }
    for (int k = tid; k < KPAD; k += 256) {
        if (k < FBINS) {
            float re = sr[k], im = si[k];
            float mag = sqrtf(re*re + im*im);
            float c, s2;
            if (mag > 1e-30f) { float inv = 1.f/mag; c = re*inv; s2 = im*inv; }
            else              { c = 1.f; s2 = 0.f; }
            g_magp[fr*KPAD + k] = mag;
            g_cosp[fr*FBINS + k] = c;
            g_sinp[fr*FBINS + k] = s2;
        } else {
            g_magp[fr*KPAD + k] = 0.f;
        }
    }
}

// ================= tensor-core GEMM (split-TF32, 3-pass) =================
// block 128x128, 8 warps (4x2), warp tile 32x64 = 2x8 m16n8k8 tiles, BK=16.

// ---- k_xg: C[ROWS,768] = magp[ROWS,528(KPAD)] @ wxp[528,768] + embrow ----
__global__ __launch_bounds__(256) void k_xg() {
    __shared__ float Ah[16][132], Al[16][132];
    __shared__ float Bh[16][132], Bl[16][132];
    const int tid = threadIdx.x;
    const int lane = tid & 31, wid = tid >> 5;
    const int wm = wid >> 1, wn = wid & 1;
    const int grp = lane >> 2, tig = lane & 3;
    const int m0 = blockIdx.y * 128, n0 = blockIdx.x * 128;

    const int am0 = tid >> 2,        aq0 = tid & 3;
    const int am1 = (tid+256) >> 2,  aq1 = (tid+256) & 3;
    const int bk0 = tid >> 5,        bq0 = tid & 31;
    const int bk1 = (tid+256) >> 5,  bq1 = (tid+256) & 31;

    float acc[2][8][4] = {};
    float4 aN0, aN1, bN0, bN1;

    // prologue (k0 = 0)
    {
        int r0 = m0 + am0, r1 = m0 + am1;
        aN0 = (r0 < ROWS) ? *(const float4*)&g_magp[r0*KPAD + 4*aq0] : make_float4(0,0,0,0);
        aN1 = (r1 < ROWS) ? *(const float4*)&g_magp[r1*KPAD + 4*aq1] : make_float4(0,0,0,0);
        bN0 = *(const float4*)&g_wxp[bk0*N3H + n0 + 4*bq0];
        bN1 = *(const float4*)&g_wxp[bk1*N3H + n0 + 4*bq1];
        float av0[4] = {aN0.x,aN0.y,aN0.z,aN0.w};
        float av1[4] = {aN1.x,aN1.y,aN1.z,aN1.w};
        #pragma unroll
        for (int j = 0; j < 4; j++) {
            float h0 = __uint_as_float(f2tf32(av0[j]));
            Ah[4*aq0+j][am0] = h0; Al[4*aq0+j][am0] = __uint_as_float(f2tf32(av0[j]-h0));
            float h1 = __uint_as_float(f2tf32(av1[j]));
            Ah[4*aq1+j][am1] = h1; Al[4*aq1+j][am1] = __uint_as_float(f2tf32(av1[j]-h1));
        }
        float4 h4, l4;
        h4.x = __uint_as_float(f2tf32(bN0.x)); l4.x = __uint_as_float(f2tf32(bN0.x-h4.x));
        h4.y = __uint_as_float(f2tf32(bN0.y)); l4.y = __uint_as_float(f2tf32(bN0.y-h4.y));
        h4.z = __uint_as_float(f2tf32(bN0.z)); l4.z = __uint_as_float(f2tf32(bN0.z-h4.z));
        h4.w = __uint_as_float(f2tf32(bN0.w)); l4.w = __uint_as_float(f2tf32(bN0.w-h4.w));
        *(float4*)&Bh[bk0][4*bq0] = h4; *(float4*)&Bl[bk0][4*bq0] = l4;
        h4.x = __uint_as_float(f2tf32(bN1.x)); l4.x = __uint_as_float(f2tf32(bN1.x-h4.x));
        h4.y = __uint_as_float(f2tf32(bN1.y)); l4.y = __uint_as_float(f2tf32(bN1.y-h4.y));
        h4.z = __uint_as_float(f2tf32(bN1.z)); l4.z = __uint_as_float(f2tf32(bN1.z-h4.z));
        h4.w = __uint_as_float(f2tf32(bN1.w)); l4.w = __uint_as_float(f2tf32(bN1.w-h4.w));
        *(float4*)&Bh[bk1][4*bq1] = h4; *(float4*)&Bl[bk1][4*bq1] = l4;
    }
    __syncthreads();

    #pragma unroll 1
    for (int it = 0; it < 33; it++) {
        if (it < 32) {
            int k0 = (it+1)*16;
            int r0 = m0 + am0, r1 = m0 + am1;
            aN0 = (r0 < ROWS) ? *(const float4*)&g_magp[r0*KPAD + k0 + 4*aq0] : make_float4(0,0,0,0);
            aN1 = (r1 < ROWS) ? *(const float4*)&g_magp[r1*KPAD + k0 + 4*aq1] : make_float4(0,0,0,0);
            bN0 = *(const float4*)&g_wxp[(k0+bk0)*N3H + n0 + 4*bq0];
            bN1 = *(const float4*)&g_wxp[(k0+bk1)*N3H + n0 + 4*bq1];
        }
        #pragma unroll
        for (int ks = 0; ks < 2; ks++) {
            const int kb = ks*8;
            unsigned afh[2][4], afl[2][4];
            #pragma unroll
            for (int mt = 0; mt < 2; mt++) {
                int rA = wm*32 + mt*16 + grp;
                afh[mt][0] = __float_as_uint(Ah[kb+tig  ][rA  ]);
                afh[mt][1] = __float_as_uint(Ah[kb+tig  ][rA+8]);
                afh[mt][2] = __float_as_uint(Ah[kb+tig+4][rA  ]);
                afh[mt][3] = __float_as_uint(Ah[kb+tig+4][rA+8]);
                afl[mt][0] = __float_as_uint(Al[kb+tig  ][rA  ]);
                afl[mt][1] = __float_as_uint(Al[kb+tig  ][rA+8]);
                afl[mt][2] = __float_as_uint(Al[kb+tig+4][rA  ]);
                afl[mt][3] = __float_as_uint(Al[kb+tig+4][rA+8]);
            }
            #pragma unroll
            for (int nt = 0; nt < 8; nt++) {
                int cB = wn*64 + nt*8 + grp;
                unsigned bh0 = __float_as_uint(Bh[kb+tig  ][cB]);
                unsigned bh1 = __float_as_uint(Bh[kb+tig+4][cB]);
                unsigned bl0 = __float_as_uint(Bl[kb+tig  ][cB]);
                unsigned bl1 = __float_as_uint(Bl[kb+tig+4][cB]);
                #pragma unroll
                for (int mt = 0; mt < 2; mt++) {
                    mma8(acc[mt][nt], afh[mt], bh0, bh1);
                    mma8(acc[mt][nt], afh[mt], bl0, bl1);
                    mma8(acc[mt][nt], afl[mt], bh0, bh1);
                }
            }
        }
        __syncthreads();
        if (it < 32) {
            float av0[4] = {aN0.x,aN0.y,aN0.z,aN0.w};
            float av1[4] = {aN1.x,aN1.y,aN1.z,aN1.w};
            #pragma unroll
            for (int j = 0; j < 4; j++) {
                float h0 = __uint_as_float(f2tf32(av0[j]));
                Ah[4*aq0+j][am0] = h0; Al[4*aq0+j][am0] = __uint_as_float(f2tf32(av0[j]-h0));
                float h1 = __uint_as_float(f2tf32(av1[j]));
                Ah[4*aq1+j][am1] = h1; Al[4*aq1+j][am1] = __uint_as_float(f2tf32(av1[j]-h1));
            }
            float4 h4, l4;
            h4.x = __uint_as_float(f2tf32(bN0.x)); l4.x = __uint_as_float(f2tf32(bN0.x-h4.x));
            h4.y = __uint_as_float(f2tf32(bN0.y)); l4.y = __uint_as_float(f2tf32(bN0.y-h4.y));
            h4.z = __uint_as_float(f2tf32(bN0.z)); l4.z = __uint_as_float(f2tf32(bN0.z-h4.z));
            h4.w = __uint_as_float(f2tf32(bN0.w)); l4.w = __uint_as_float(f2tf32(bN0.w-h4.w));
            *(float4*)&Bh[bk0][4*bq0] = h4; *(float4*)&Bl[bk0][4*bq0] = l4;
            h4.x = __uint_as_float(f2tf32(bN1.x)); l4.x = __uint_as_float(f2tf32(bN1.x-h4.x));
            h4.y = __uint_as_float(f2tf32(bN1.y)); l4.y = __uint_as_float(f2tf32(bN1.y-h4.y));
            h4.z = __uint_as_float(f2tf32(bN1.z)); l4.z = __uint_as_float(f2tf32(bN1.z-h4.z));
            h4.w = __uint_as_float(f2tf32(bN1.w)); l4.w = __uint_as_float(f2tf32(bN1.w-h4.w));
            *(float4*)&Bh[bk1][4*bq1] = h4; *(float4*)&Bl[bk1][4*bq1] = l4;
            __syncthreads();
        }
    }

    #pragma unroll
    for (int mt = 0; mt < 2; mt++) {
        #pragma unroll
        for (int nt = 0; nt < 8; nt++) {
            int row0 = m0 + wm*32 + mt*16 + grp;
            int col0 = n0 + wn*64 + nt*8 + 2*tig;
            if (row0 < ROWS) {
                int b = row0 / CPB;
                g_xg[row0*N3H + col0  ] = acc[mt][nt][0] + g_embrow[b*N3H + col0  ];
                g_xg[row0*N3H + col0+1] = acc[mt][nt][1] + g_embrow[b*N3H + col0+1];
            }
            int row1 = row0 + 8;
            if (row1 < ROWS) {
                int b = row1 / CPB;
                g_xg[row1*N3H + col0  ] = acc[mt][nt][2] + g_embrow[b*N3H + col0  ];
                g_xg[row1*N3H + col0+1] = acc[mt][nt][3] + g_embrow[b*N3H + col0+1];
            }
        }
    }
}

// ---- k_proj: C[ROWS,1026] = hs[ROWS,256] @ pwp[256,1152] + pb ----
__global__ __launch_bounds__(256) void k_proj(const float* __restrict__ pb) {
    __shared__ float Ah[16][132], Al[16][132];
    __shared__ float Bh[16][132], Bl[16][132];
    const int tid = threadIdx.x;
    const int lane = tid & 31, wid = tid >> 5;
    const int wm = wid >> 1, wn = wid & 1;
    const int grp = lane >> 2, tig = lane & 3;
    const int m0 = blockIdx.y * 128, n0 = blockIdx.x * 128;

    const int am0 = tid >> 2,        aq0 = tid & 3;
    const int am1 = (tid+256) >> 2,  aq1 = (tid+256) & 3;
    const int bk0 = tid >> 5,        bq0 = tid & 31;
    const int bk1 = (tid+256) >> 5,  bq1 = (tid+256) & 31;

    float acc[2][8][4] = {};
    float4 aN0, aN1, bN0, bN1;

    {
        int r0 = m0 + am0, r1 = m0 + am1;
        aN0 = (r0 < ROWS) ? *(const float4*)&g_hs[r0*HDIM + 4*aq0] : make_float4(0,0,0,0);
        aN1 = (r1 < ROWS) ? *(const float4*)&g_hs[r1*HDIM + 4*aq1] : make_float4(0,0,0,0);
        bN0 = *(const float4*)&g_pwp[bk0*PWLD + n0 + 4*bq0];
        bN1 = *(const float4*)&g_pwp[bk1*PWLD + n0 + 4*bq1];
        float av0[4] = {aN0.x,aN0.y,aN0.z,aN0.w};
        float av1[4] = {aN1.x,aN1.y,aN1.z,aN1.w};
        #pragma unroll
        for (int j = 0; j < 4; j++) {
            float h0 = __uint_as_float(f2tf32(av0[j]));
            Ah[4*aq0+j][am0] = h0; Al[4*aq0+j][am0] = __uint_as_float(f2tf32(av0[j]-h0));
            float h1 = __uint_as_float(f2tf32(av1[j]));
            Ah[4*aq1+j][am1] = h1; Al[4*aq1+j][am1] = __uint_as_float(f2tf32(av1[j]-h1));
        }
        float4 h4, l4;
        h4.x = __uint_as_float(f2tf32(bN0.x)); l4.x = __uint_as_float(f2tf32(bN0.x-h4.x));
        h4.y = __uint_as_float(f2tf32(bN0.y)); l4.y = __uint_as_float(f2tf32(bN0.y-h4.y));
        h4.z = __uint_as_float(f2tf32(bN0.z)); l4.z = __uint_as_float(f2tf32(bN0.z-h4.z));
        h4.w = __uint_as_float(f2tf32(bN0.w)); l4.w = __uint_as_float(f2tf32(bN0.w-h4.w));
        *(float4*)&Bh[bk0][4*bq0] = h4; *(float4*)&Bl[bk0][4*bq0] = l4;
        h4.x = __uint_as_float(f2tf32(bN1.x)); l4.x = __uint_as_float(f2tf32(bN1.x-h4.x));
        h4.y = __uint_as_float(f2tf32(bN1.y)); l4.y = __uint_as_float(f2tf32(bN1.y-h4.y));
        h4.z = __uint_as_float(f2tf32(bN1.z)); l4.z = __uint_as_float(f2tf32(bN1.z-h4.z));
        h4.w = __uint_as_float(f2tf32(bN1.w)); l4.w = __uint_as_float(f2tf32(bN1.w-h4.w));
        *(float4*)&Bh[bk1][4*bq1] = h4; *(float4*)&Bl[bk1][4*bq1] = l4;
    }
    __syncthreads();

    #pragma unroll 1
    for (int it = 0; it < 16; it++) {
        if (it < 15) {
            int k0 = (it+1)*16;
            int r0 = m0 + am0, r1 = m0 + am1;
            aN0 = (r0 < ROWS) ? *(const float4*)&g_hs[r0*HDIM + k0 + 4*aq0] : make_float4(0,0,0,0);
            aN1 = (r1 < ROWS) ? *(const float4*)&g_hs[r1*HDIM + k0 + 4*aq1] : make_float4(0,0,0,0);
            bN0 = *(const float4*)&g_pwp[(k0+bk0)*PWLD + n0 + 4*bq0];
            bN1 = *(const float4*)&g_pwp[(k0+bk1)*PWLD + n0 + 4*bq1];
        }
        #pragma unroll
        for (int ks = 0; ks < 2; ks++) {
            const int kb = ks*8;
            unsigned afh[2][4], afl[2][4];
            #pragma unroll
            for (int mt = 0; mt < 2; mt++) {
                int rA = wm*32 + mt*16 + grp;
                afh[mt][0] = __float_as_uint(Ah[kb+tig  ][rA  ]);
                afh[mt][1] = __float_as_uint(Ah[kb+tig  ][rA+8]);
                afh[mt][2] = __float_as_uint(Ah[kb+tig+4][rA  ]);
                afh[mt][3] = __float_as_uint(Ah[kb+tig+4][rA+8]);
                afl[mt][0] = __float_as_uint(Al[kb+tig  ][rA  ]);
                afl[mt][1] = __float_as_uint(Al[kb+tig  ][rA+8]);
                afl[mt][2] = __float_as_uint(Al[kb+tig+4][rA  ]);
                afl[mt][3] = __float_as_uint(Al[kb+tig+4][rA+8]);
            }
            #pragma unroll
            for (int nt = 0; nt < 8; nt++) {
                int cB = wn*64 + nt*8 + grp;
                unsigned bh0 = __float_as_uint(Bh[kb+tig  ][cB]);
                unsigned bh1 = __float_as_uint(Bh[kb+tig+4][cB]);
                unsigned bl0 = __float_as_uint(Bl[kb+tig  ][cB]);
                unsigned bl1 = __float_as_uint(Bl[kb+tig+4][cB]);
                #pragma unroll
                for (int mt = 0; mt < 2; mt++) {
                    mma8(acc[mt][nt], afh[mt], bh0, bh1);
                    mma8(acc[mt][nt], afh[mt], bl0, bl1);
                    mma8(acc[mt][nt], afl[mt], bh0, bh1);
                }
            }
        }
        __syncthreads();
        if (it < 15) {
            float av0[4] = {aN0.x,aN0.y,aN0.z,aN0.w};
            float av1[4] = {aN1.x,aN1.y,aN1.z,aN1.w};
            #pragma unroll
            for (int j = 0; j < 4; j++) {
                float h0 = __uint_as_float(f2tf32(av0[j]));
                Ah[4*aq0+j][am0] = h0; Al[4*aq0+j][am0] = __uint_as_float(f2tf32(av0[j]-h0));
                float h1 = __uint_as_float(f2tf32(av1[j]));
                Ah[4*aq1+j][am1] = h1; Al[4*aq1+j][am1] = __uint_as_float(f2tf32(av1[j]-h1));
            }
            float4 h4, l4;
            h4.x = __uint_as_float(f2tf32(bN0.x)); l4.x = __uint_as_float(f2tf32(bN0.x-h4.x));
            h4.y = __uint_as_float(f2tf32(bN0.y)); l4.y = __uint_as_float(f2tf32(bN0.y-h4.y));
            h4.z = __uint_as_float(f2tf32(bN0.z)); l4.z = __uint_as_float(f2tf32(bN0.z-h4.z));
            h4.w = __uint_as_float(f2tf32(bN0.w)); l4.w = __uint_as_float(f2tf32(bN0.w-h4.w));
            *(float4*)&Bh[bk0][4*bq0] = h4; *(float4*)&Bl[bk0][4*bq0] = l4;
            h4.x = __uint_as_float(f2tf32(bN1.x)); l4.x = __uint_as_float(f2tf32(bN1.x-h4.x));
            h4.y = __uint_as_float(f2tf32(bN1.y)); l4.y = __uint_as_float(f2tf32(bN1.y-h4.y));
            h4.z = __uint_as_float(f2tf32(bN1.z)); l4.z = __uint_as_float(f2tf32(bN1.z-h4.z));
            h4.w = __uint_as_float(f2tf32(bN1.w)); l4.w = __uint_as_float(f2tf32(bN1.w-h4.w));
            *(float4*)&Bh[bk1][4*bq1] = h4; *(float4*)&Bl[bk1][4*bq1] = l4;
            __syncthreads();
        }
    }

    #pragma unroll
    for (int mt = 0; mt < 2; mt++) {
        #pragma unroll
        for (int nt = 0; nt < 8; nt++) {
            int row0 = m0 + wm*32 + mt*16 + grp;
            int col0 = n0 + wn*64 + nt*8 + 2*tig;
            if (row0 < ROWS) {
                if (col0   < NGB) g_gb[row0*NGB + col0  ] = acc[mt][nt][0] + pb[col0  ];
                if (col0+1 < NGB) g_gb[row0*NGB + col0+1] = acc[mt][nt][1] + pb[col0+1];
            }
            int row1 = row0 + 8;
            if (row1 < ROWS) {
                if (col0   < NGB) g_gb[row1*NGB + col0  ] = acc[mt][nt][2] + pb[col0  ];
                if (col0+1 < NGB) g_gb[row1*NGB + col0+1] = acc[mt][nt][3] + pb[col0+1];
            }
        }
    }
}

// ---------------- one GRU step (unchanged) ----------------
__global__ void k_gru(const float* __restrict__ wh,
                      const float* __restrict__ gbias, int t) {
    __shared__ float As[16][33];
    __shared__ float Bs[3][16][65];
    const int sq0 = blockIdx.y * 32;
    const int c0  = blockIdx.x * 64;
    const int tid = threadIdx.x;
    const int ty = tid >> 4, tx = tid & 15;
    float acc[3][2][4] = {};
    if (t > 0) {
        for (int k0 = 0; k0 < HDIM; k0 += 16) {
            #pragma unroll
            for (int i = 0; i < 2; i++) {
                int lin = tid + i*256;
                int mm = lin >> 4, kk = lin & 15;
                int sq = sq0 + mm;
                As[kk][mm] = (sq < SEQ) ? g_hs[(sq*NF + t - 1)*HDIM + k0 + kk] : 0.f;
            }
            #pragma unroll
            for (int i = 0; i < 12; i++) {
                int lin = tid + i*256;
                int gg = lin >> 10;
                int r2 = lin & 1023;
                int kk = r2 >> 6, nn = r2 & 63;
                Bs[gg][kk][nn] = wh[(k0+kk)*N3H + gg*HDIM + c0 + nn];
            }
            __syncthreads();
            #pragma unroll
            for (int kk = 0; kk < 16; kk++) {
                float a0 = As[kk][ty*2], a1 = As[kk][ty*2 + 1];
                #pragma unroll
                for (int gg = 0; gg < 3; gg++) {
                    #pragma unroll
                    for (int j = 0; j < 4; j++) {
                        float bvv = Bs[gg][kk][tx*4 + j];
                        acc[gg][0][j] += a0*bvv;
                        acc[gg][1][j] += a1*bvv;
                    }
                }
            }
            __syncthreads();
        }
    }
    #pragma unroll
    for (int i = 0; i < 2; i++) {
        int sq = sq0 + ty*2 + i;
        if (sq >= SEQ) continue;
        const float* xg = &g_xg[(sq*NF + t)*N3H];
        int hbase = (sq*NF + t)*HDIM;
        int pbase = (sq*NF + t - 1)*HDIM;
        #pragma unroll
        for (int j = 0; j < 4; j++) {
            int c = c0 + tx*4 + j;
            float z = sigf(xg[c]           + acc[0][i][j] + gbias[c]);
            float r = sigf(xg[HDIM + c]    + acc[1][i][j] + gbias[HDIM + c]);
            float n = tanhf(xg[2*HDIM + c] + r*(acc[2][i][j] + gbias[2*HDIM + c]));
            float hp = (t > 0) ? g_hs[pbase + c] : 0.f;
            g_hs[hbase + c] = (1.f - z)*n + z*hp;
        }
    }
}

// ---------------- modulate + inverse FFT + window ----------------
__global__ void k_modinv() {
    __shared__ float sre[FBINS], sim[FBINS];
    __shared__ float sr[NFFT], si[NFFT];
    __shared__ float twr[512], twi[512];
    const int fr  = blockIdx.x;
    const int tid = threadIdx.x;

    for (int k = tid; k < 512; k += 256) { twr[k] = g_twr[k]; twi[k] = g_twi[k]; }
    for (int k = tid; k < FBINS; k += 256) {
        float mag   = g_magp[fr*KPAD + k];
        float gamma = g_gb[fr*NGB + k];
        float beta  = g_gb[fr*NGB + FBINS + k];
        float mm = gamma*mag + beta;
        sre[k] = mm * g_cosp[fr*FBINS + k];
        sim[k] = mm * g_sinp[fr*FBINS + k];
    }
    __syncthreads();
    for (int n = tid; n < NFFT; n += 256) {
        float re, im;
        if (n <= 512) { re = sre[n];        im =  sim[n]; }
        else          { re = sre[NFFT - n]; im = -sim[NFFT - n]; }
        int j = __brev((unsigned)n) >> 22;
        sr[j] = re; si[j] = im;
    }
    __syncthreads();
    for (int s = 1; s <= 10; s++) {
        int half = 1 << (s-1);
        for (int t = tid; t < 512; t += 256) {
            int pos = t & (half-1);
            int grp = t >> (s-1);
            int i1 = (grp << s) + pos;
            int i2 = i1 + half;
            int ti_ = pos << (10 - s);
            float wr = twr[ti_], wi = -twi[ti_];
            float xr = sr[i2], xi = si[i2];
            float tr = wr*xr - wi*xi;
            float tq = wr*xi + wi*xr;
            sr[i2] = sr[i1] - tr; si[i2] = si[i1] - tq;
            sr[i1] += tr;         si[i1] += tq;
        }
        __syncthreads();
    }
    const float invn = 1.f/(float)NFFT;
    for (int n = tid; n < NFFT; n += 256)
        g_y[fr*NFFT + n] = sr[n]*invn*g_win[n];
}

// ---------------- overlap-add ----------------
__global__ void k_overlap(float* __restrict__ out) {
    const int t = blockIdx.x*blockDim.x + threadIdx.x;
    const int b = blockIdx.y;
    if (t >= TSZ) return;
    int ci_hi = t / STRIDE; if (ci_hi > NCH-1) ci_hi = NCH-1;
    int v = t - (CHUNK - 1);
    int ci_lo = (v <= 0) ? 0 : (v + STRIDE - 1)/STRIDE;
    float acc = 0.f;
    for (int ci = ci_lo; ci <= ci_hi; ci++) {
        int n = t - ci*STRIDE;
        int fi_hi = n >> 8; if (fi_hi > NF-1) fi_hi = NF-1;
        int w = n - (NFFT - 1);
        int fi_lo = (w <= 0) ? 0 : (w + HOP - 1) >> 8;
        float s = 0.f;
        for (int fi = fi_lo; fi <= fi_hi; fi++)
            s += g_y[(((b*NCH + ci)*NF) + fi)*NFFT + n - fi*HOP];
        acc += s / fmaxf(g_wsum[n], 1e-8f);
    }
    out[b*TSZ + t] = acc;
}

// ---------------- launch ----------------
extern "C" void kernel_launch(void* const* d_in, const int* in_sizes, int n_in,
                              void* d_out, int out_size) {
    const float* audio     = (const float*)d_in[0];
    const float* emb_table = (const float*)d_in[1];
    const float* gru_wx    = (const float*)d_in[2];
    const float* gru_wh    = (const float*)d_in[3];
    const float* gru_b     = (const float*)d_in[4];
    const float* proj_w    = (const float*)d_in[5];
    const float* proj_b    = (const float*)d_in[6];
    const int*   effect_id = (const int*)  d_in[7];
    float* out = (float*)d_out;

    k_tables<<<(CHUNK + 255)/256, 256>>>();                        // 1
    k_prep<<<NBWX + NBPW + BATCH, 256>>>(gru_wx, proj_w,
                                         emb_table, effect_id);    // 2
    k_fwdfft<<<ROWS, 256>>>(audio);                                // 3
    k_xg<<<dim3(N3H/128, (ROWS + 127)/128), 256>>>();              // 4 <- profiled
    for (int t = 0; t < NF; t++)
        k_gru<<<dim3(HDIM/64, (SEQ + 31)/32), 256>>>(gru_wh, gru_b, t);
    k_proj<<<dim3(PWLD/128, (ROWS + 127)/128), 256>>>(proj_b);
    k_modinv<<<ROWS, 256>>>();
    k_overlap<<<dim3((TSZ + 255)/256, BATCH), 256>>>(out);
}

// round 6
// speedup vs baseline: 1.4086x; 1.4086x over previous
#include <cuda_runtime.h>
#include <cuda_bf16.h>
#include <math.h>

// ---------------- problem constants ----------------
#define TSZ    480000
#define BATCH  8
#define CHUNK  4096
#define STRIDE 3072
#define NCH    157
#define NF     13
#define NFFT   1024
#define HOP    256
#define FBINS  513
#define HDIM   256
#define EDIM   128
#define N3H    768
#define SEQ    (BATCH*NCH)   // 1256
#define ROWS   (SEQ*NF)      // 16328
#define CPB    (NCH*NF)      // 2041
#define KPAD   528
#define PWLD   1152
#define NGB    1026
#define PI_F   3.14159265358979323846f

// ---------------- scratch ----------------
__device__ __nv_bfloat16 g_magh[ROWS*KPAD], g_magl[ROWS*KPAD];
__device__ float g_cosp[ROWS*FBINS];
__device__ float g_sinp[ROWS*FBINS];
__device__ float g_xg  [ROWS*N3H];
__device__ float g_hs  [ROWS*HDIM];
__device__ __nv_bfloat16 g_hsh[ROWS*HDIM], g_hsl[ROWS*HDIM];
__device__ float g_gb  [ROWS*NGB];
__device__ float g_y   [ROWS*NFFT];
__device__ float g_embrow[BATCH*N3H];
__device__ float g_wsum[CHUNK];
__device__ __nv_bfloat16 g_wxh[N3H*KPAD], g_wxl[N3H*KPAD];   // transposed [n][k]
__device__ __nv_bfloat16 g_pwh[PWLD*HDIM], g_pwl[PWLD*HDIM]; // transposed [n][k]
__device__ float g_twr[512], g_twi[512];
__device__ float g_win[NFFT];

__device__ __forceinline__ float sigf(float x) { return 1.f/(1.f + expf(-x)); }

__device__ __forceinline__ void bsplit(float v, __nv_bfloat16& h, __nv_bfloat16& l) {
    h = __float2bfloat16(v);
    l = __float2bfloat16(v - __bfloat162float(h));
}

__device__ __forceinline__ void mmab(float* c, const unsigned* a, unsigned b0, unsigned b1) {
    asm volatile("mma.sync.aligned.m16n8k16.row.col.f32.bf16.bf16.f32 "
        "{%0,%1,%2,%3}, {%4,%5,%6,%7}, {%8,%9}, {%0,%1,%2,%3};"
        : "+f"(c[0]), "+f"(c[1]), "+f"(c[2]), "+f"(c[3])
        : "r"(a[0]), "r"(a[1]), "r"(a[2]), "r"(a[3]), "r"(b0), "r"(b1));
}
__device__ __forceinline__ void cpa16(unsigned d, const void* s, int sz) {
    asm volatile("cp.async.ca.shared.global [%0], [%1], 16, %2;" :: "r"(d), "l"(s), "r"(sz));
}
#define CPA_COMMIT() asm volatile("cp.async.commit_group;")
#define CPA_WAIT()   asm volatile("cp.async.wait_all;" ::: "memory")

// ---------------- tables ----------------
__global__ void k_tables() {
    int i = blockIdx.x*blockDim.x + threadIdx.x;
    if (i < 512) {
        float s, c; sincosf(-(2.f*PI_F/NFFT)*i, &s, &c);
        g_twr[i] = c; g_twi[i] = s;
    }
    if (i < NFFT)
        g_win[i] = 0.5f - 0.5f*cosf((2.f*PI_F/NFFT)*i);
    if (i < CHUNK) {
        float ws = 0.f;
        for (int fi = 0; fi < NF; fi++) {
            int d = i - fi*HOP;
            if (d >= 0 && d < NFFT) {
                float w = 0.5f - 0.5f*cosf((2.f*PI_F/NFFT)*d);
                ws += w*w;
            }
        }
        g_wsum[i] = ws;
    }
}

// ---------------- prep: split+transpose weights ----------------
#define NWX (N3H*KPAD)     // 405504
#define NPW (PWLD*HDIM)    // 294912
__global__ void k_prep_w(const float* __restrict__ wx,
                         const float* __restrict__ pw) {
    int i = blockIdx.x*blockDim.x + threadIdx.x;
    if (i < NWX) {
        int n = i / KPAD, k = i % KPAD;
        float v = (k < FBINS) ? wx[k*N3H + n] : 0.f;
        bsplit(v, g_wxh[i], g_wxl[i]);
    } else if (i < NWX + NPW) {
        int j = i - NWX;
        int n = j / HDIM, k = j % HDIM;
        float v = (n < NGB) ? pw[k*NGB + n] : 0.f;
        bsplit(v, g_pwh[j], g_pwl[j]);
    }
}

// ---------------- embrow ----------------
__global__ void k_prep_e(const float* __restrict__ emb_table,
                         const float* __restrict__ wx,
                         const int*   __restrict__ effect_id) {
    __shared__ float se[EDIM];
    int b = blockIdx.x, tid = threadIdx.x;
    if (tid < EDIM) se[tid] = emb_table[effect_id[b]*EDIM + tid];
    __syncthreads();
    for (int j = tid; j < N3H; j += 256) {
        float acc = 0.f;
        #pragma unroll 8
        for (int k = 0; k < EDIM; k++)
            acc += se[k] * wx[(FBINS + k)*N3H + j];
        g_embrow[b*N3H + j] = acc;
    }
}

// ---------------- forward STFT: 2 real frames per complex FFT ----------------
__global__ void k_fwdfft(const float* __restrict__ audio) {
    __shared__ float sr[NFFT], si[NFFT];
    __shared__ float twr[512], twi[512];
    const int pr  = blockIdx.x;
    const int tid = threadIdx.x;
    const int fr0 = 2*pr, fr1 = fr0 + 1;
    const int b0 = fr0 / CPB, r0 = fr0 % CPB;
    const int b1 = fr1 / CPB, r1 = fr1 % CPB;
    const int base0 = (r0/NF)*STRIDE + (r0%NF)*HOP;
    const int base1 = (r1/NF)*STRIDE + (r1%NF)*HOP;

    for (int k = tid; k < 512; k += 256) { twr[k] = g_twr[k]; twi[k] = g_twi[k]; }
    for (int n = tid; n < NFFT; n += 256) {
        int s0 = base0 + n, s1 = base1 + n;
        float v0 = (s0 < TSZ) ? audio[b0*TSZ + s0] : 0.f;
        float v1 = (s1 < TSZ) ? audio[b1*TSZ + s1] : 0.f;
        float w = g_win[n];
        int j = __brev((unsigned)n) >> 22;
        sr[j] = v0*w; si[j] = v1*w;
    }
    __syncthreads();
    for (int s = 1; s <= 10; s++) {
        int half = 1 << (s-1);
        for (int t = tid; t < 512; t += 256) {
            int pos = t & (half-1);
            int grp = t >> (s-1);
            int i1 = (grp << s) + pos;
            int i2 = i1 + half;
            int ti_ = pos << (10 - s);
            float wr = twr[ti_], wi = twi[ti_];
            float xr = sr[i2], xi = si[i2];
            float tr = wr*xr - wi*xi;
            float tq = wr*xi + wi*xr;
            sr[i2] = sr[i1] - tr; si[i2] = si[i1] - tq;
            sr[i1] += tr;         si[i1] += tq;
        }
        __syncthreads();
    }
    // Unpack two real spectra via Hermitian symmetry
    for (int k = tid; k < KPAD; k += 256) {
        if (k < FBINS) {
            int m = (NFFT - k) & (NFFT-1);
            float rek = sr[k], imk = si[k];
            float rem = sr[m], imm = si[m];
            float re0 = 0.5f*(rek + rem), i0 = 0.5f*(imk - imm);
            float re1 = 0.5f*(imk + imm), i1 = 0.5f*(rem - rek);
            float mag0 = sqrtf(re0*re0 + i0*i0);
            float c0, s0;
            if (mag0 > 1e-30f) { float inv = 1.f/mag0; c0 = re0*inv; s0 = i0*inv; }
            else               { c0 = 1.f; s0 = 0.f; }
            float mag1 = sqrtf(re1*re1 + i1*i1);
            float c1, s1;
            if (mag1 > 1e-30f) { float inv = 1.f/mag1; c1 = re1*inv; s1 = i1*inv; }
            else               { c1 = 1.f; s1 = 0.f; }
            bsplit(mag0, g_magh[fr0*KPAD + k], g_magl[fr0*KPAD + k]);
            bsplit(mag1, g_magh[fr1*KPAD + k], g_magl[fr1*KPAD + k]);
            g_cosp[fr0*FBINS + k] = c0; g_sinp[fr0*FBINS + k] = s0;
            g_cosp[fr1*FBINS + k] = c1; g_sinp[fr1*FBINS + k] = s1;
        } else {
            __nv_bfloat16 z = __float2bfloat16(0.f);
            g_magh[fr0*KPAD + k] = z; g_magl[fr0*KPAD + k] = z;
            g_magh[fr1*KPAD + k] = z; g_magl[fr1*KPAD + k] = z;
        }
    }
}

// ================= bf16-split 3-pass tensor GEMM =================
// block 128x128, 8 warps (4x2), warp tile 32x64 = 2x8 m16n8k16 tiles, BK=16.
// smem (dynamic, 48KB): uint planes [2buf][128][12]: Ah, Al, Bh, Bl.
#define SM_PLANE (128*12)          // uints per plane-buffer
#define SM_AH(p,r,c) smem_u[((p)*128 + (r))*12 + (c)]
#define SM_AL(p,r,c) smem_u[SM_PLANE*2 + ((p)*128 + (r))*12 + (c)]
#define SM_BH(p,r,c) smem_u[SM_PLANE*4 + ((p)*128 + (r))*12 + (c)]
#define SM_BL(p,r,c) smem_u[SM_PLANE*6 + ((p)*128 + (r))*12 + (c)]
#define SMEM_GEMM_BYTES (SM_PLANE*8*4)   // 49152 = 48KB (default limit, no opt-in needed)

template<int NIT, int KSTRIDE>
__device__ __forceinline__ void gemm_core(
    unsigned* smem_u,
    const __nv_bfloat16* Ah_g, const __nv_bfloat16* Al_g, int a_row_max,
    const __nv_bfloat16* Bh_g, const __nv_bfloat16* Bl_g,
    int m0, int n0, float acc[2][8][4])
{
    const int tid = threadIdx.x;
    const int lane = tid & 31, wid = tid >> 5;
    const int wm = wid >> 1, wn = wid & 1;
    const int grp = lane >> 2, tig = lane & 3;
    const int row = tid >> 1, half = tid & 1;
    const int arow = m0 + row;
    const int asz = (arow < a_row_max) ? 16 : 0;
    const int brow = n0 + row;

    unsigned sbase = (unsigned)__cvta_generic_to_shared(smem_u);
    unsigned off = (row*12 + half*4)*4;
    unsigned dAh = sbase + off;
    unsigned dAl = sbase + SM_PLANE*2*4 + off;
    unsigned dBh = sbase + SM_PLANE*4*4 + off;
    unsigned dBl = sbase + SM_PLANE*6*4 + off;
    const unsigned bufB = 128*12*4;

    // prologue
    cpa16(dAh, Ah_g + (size_t)arow*KSTRIDE + half*8, asz);
    cpa16(dAl, Al_g + (size_t)arow*KSTRIDE + half*8, asz);
    cpa16(dBh, Bh_g + (size_t)brow*KSTRIDE + half*8, 16);
    cpa16(dBl, Bl_g + (size_t)brow*KSTRIDE + half*8, 16);
    CPA_COMMIT();
    CPA_WAIT();
    __syncthreads();

    #pragma unroll 1
    for (int it = 0; it < NIT; it++) {
        int p = it & 1, q = p ^ 1;
        if (it + 1 < NIT) {
            int k0 = (it+1)*16;
            cpa16(dAh + q*bufB, Ah_g + (size_t)arow*KSTRIDE + k0 + half*8, asz);
            cpa16(dAl + q*bufB, Al_g + (size_t)arow*KSTRIDE + k0 + half*8, asz);
            cpa16(dBh + q*bufB, Bh_g + (size_t)brow*KSTRIDE + k0 + half*8, 16);
            cpa16(dBl + q*bufB, Bl_g + (size_t)brow*KSTRIDE + k0 + half*8, 16);
            CPA_COMMIT();
        }
        unsigned afh[2][4], afl[2][4];
        #pragma unroll
        for (int mt = 0; mt < 2; mt++) {
            int rA = wm*32 + mt*16 + grp;
            afh[mt][0] = SM_AH(p, rA,   tig);
            afh[mt][1] = SM_AH(p, rA+8, tig);
            afh[mt][2] = SM_AH(p, rA,   tig+4);
            afh[mt][3] = SM_AH(p, rA+8, tig+4);
            afl[mt][0] = SM_AL(p, rA,   tig);
            afl[mt][1] = SM_AL(p, rA+8, tig);
            afl[mt][2] = SM_AL(p, rA,   tig+4);
            afl[mt][3] = SM_AL(p, rA+8, tig+4);
        }
        #pragma unroll
        for (int nt = 0; nt < 8; nt++) {
            int cB = wn*64 + nt*8 + grp;
            unsigned bh0 = SM_BH(p, cB, tig);
            unsigned bh1 = SM_BH(p, cB, tig+4);
            unsigned bl0 = SM_BL(p, cB, tig);
            unsigned bl1 = SM_BL(p, cB, tig+4);
            #pragma unroll
            for (int mt = 0; mt < 2; mt++) {
                mmab(acc[mt][nt], afh[mt], bh0, bh1);
                mmab(acc[mt][nt], afh[mt], bl0, bl1);
                mmab(acc[mt][nt], afl[mt], bh0, bh1);
            }
        }
        if (it + 1 < NIT) CPA_WAIT();
        __syncthreads();
    }
}

// ---- k_xg: C[ROWS,768] = mag @ wx + embrow ----
__global__ __launch_bounds__(256, 2) void k_xg() {
    extern __shared__ unsigned smem_u[];
    const int tid = threadIdx.x;
    const int lane = tid & 31, wid = tid >> 5;
    const int wm = wid >> 1, wn = wid & 1;
    const int grp = lane >> 2, tig = lane & 3;
    const int m0 = blockIdx.y * 128, n0 = blockIdx.x * 128;
    float acc[2][8][4] = {};
    gemm_core<33, KPAD>(smem_u, g_magh, g_magl, ROWS, g_wxh, g_wxl, m0, n0, acc);
    #pragma unroll
    for (int mt = 0; mt < 2; mt++) {
        #pragma unroll
        for (int nt = 0; nt < 8; nt++) {
            int row0 = m0 + wm*32 + mt*16 + grp;
            int col0 = n0 + wn*64 + nt*8 + 2*tig;
            if (row0 < ROWS) {
                int b = row0 / CPB;
                g_xg[row0*N3H + col0  ] = acc[mt][nt][0] + g_embrow[b*N3H + col0  ];
                g_xg[row0*N3H + col0+1] = acc[mt][nt][1] + g_embrow[b*N3H + col0+1];
            }
            int row1 = row0 + 8;
            if (row1 < ROWS) {
                int b = row1 / CPB;
                g_xg[row1*N3H + col0  ] = acc[mt][nt][2] + g_embrow[b*N3H + col0  ];
                g_xg[row1*N3H + col0+1] = acc[mt][nt][3] + g_embrow[b*N3H + col0+1];
            }
        }
    }
}

// ---- k_proj: C[ROWS,1026] = hs @ pw + pb ----
__global__ __launch_bounds__(256, 2) void k_proj(const float* __restrict__ pb) {
    extern __shared__ unsigned smem_u[];
    const int tid = threadIdx.x;
    const int lane = tid & 31, wid = tid >> 5;
    const int wm = wid >> 1, wn = wid & 1;
    const int grp = lane >> 2, tig = lane & 3;
    const int m0 = blockIdx.y * 128, n0 = blockIdx.x * 128;
    float acc[2][8][4] = {};
    gemm_core<16, HDIM>(smem_u, g_hsh, g_hsl, ROWS, g_pwh, g_pwl, m0, n0, acc);
    #pragma unroll
    for (int mt = 0; mt < 2; mt++) {
        #pragma unroll
        for (int nt = 0; nt < 8; nt++) {
            int row0 = m0 + wm*32 + mt*16 + grp;
            int col0 = n0 + wn*64 + nt*8 + 2*tig;
            if (row0 < ROWS) {
                if (col0   < NGB) g_gb[row0*NGB + col0  ] = acc[mt][nt][0] + pb[col0  ];
                if (col0+1 < NGB) g_gb[row0*NGB + col0+1] = acc[mt][nt][1] + pb[col0+1];
            }
            int row1 = row0 + 8;
            if (row1 < ROWS) {
                if (col0   < NGB) g_gb[row1*NGB + col0  ] = acc[mt][nt][2] + pb[col0  ];
                if (col0+1 < NGB) g_gb[row1*NGB + col0+1] = acc[mt][nt][3] + pb[col0+1];
            }
        }
    }
}

// ---------------- one GRU step ----------------
__global__ void k_gru(const float* __restrict__ wh,
                      const float* __restrict__ gbias, int t) {
    __shared__ float As[16][33];
    __shared__ float Bs[3][16][65];
    const int sq0 = blockIdx.y * 32;
    const int c0  = blockIdx.x * 64;
    const int tid = threadIdx.x;
    const int ty = tid >> 4, tx = tid & 15;
    float acc[3][2][4] = {};
    if (t > 0) {
        for (int k0 = 0; k0 < HDIM; k0 += 16) {
            #pragma unroll
            for (int i = 0; i < 2; i++) {
                int lin = tid + i*256;
                int mm = lin >> 4, kk = lin & 15;
                int sq = sq0 + mm;
                As[kk][mm] = (sq < SEQ) ? g_hs[(sq*NF + t - 1)*HDIM + k0 + kk] : 0.f;
            }
            #pragma unroll
            for (int i = 0; i < 12; i++) {
                int lin = tid + i*256;
                int gg = lin >> 10;
                int r2 = lin & 1023;
                int kk = r2 >> 6, nn = r2 & 63;
                Bs[gg][kk][nn] = wh[(k0+kk)*N3H + gg*HDIM + c0 + nn];
            }
            __syncthreads();
            #pragma unroll
            for (int kk = 0; kk < 16; kk++) {
                float a0 = As[kk][ty*2], a1 = As[kk][ty*2 + 1];
                #pragma unroll
                for (int gg = 0; gg < 3; gg++) {
                    #pragma unroll
                    for (int j = 0; j < 4; j++) {
                        float bvv = Bs[gg][kk][tx*4 + j];
                        acc[gg][0][j] += a0*bvv;
                        acc[gg][1][j] += a1*bvv;
                    }
                }
            }
            __syncthreads();
        }
    }
    #pragma unroll
    for (int i = 0; i < 2; i++) {
        int sq = sq0 + ty*2 + i;
        if (sq >= SEQ) continue;
        const float* xg = &g_xg[(sq*NF + t)*N3H];
        int hbase = (sq*NF + t)*HDIM;
        int pbase = (sq*NF + t - 1)*HDIM;
        #pragma unroll
        for (int j = 0; j < 4; j++) {
            int c = c0 + tx*4 + j;
            float z = sigf(xg[c]           + acc[0][i][j] + gbias[c]);
            float r = sigf(xg[HDIM + c]    + acc[1][i][j] + gbias[HDIM + c]);
            float n = tanhf(xg[2*HDIM + c] + r*(acc[2][i][j] + gbias[2*HDIM + c]));
            float hp = (t > 0) ? g_hs[pbase + c] : 0.f;
            float h = (1.f - z)*n + z*hp;
            g_hs[hbase + c] = h;
            bsplit(h, g_hsh[hbase + c], g_hsl[hbase + c]);
        }
    }
}

// ---------------- modulate + inverse FFT: 2 frames per complex iFFT ----------------
__global__ void k_modinv() {
    __shared__ float sre0[FBINS], sim0[FBINS], sre1[FBINS], sim1[FBINS];
    __shared__ float sr[NFFT], si[NFFT];
    __shared__ float twr[512], twi[512];
    const int pr  = blockIdx.x;
    const int tid = threadIdx.x;
    const int fr0 = 2*pr, fr1 = fr0 + 1;

    for (int k = tid; k < 512; k += 256) { twr[k] = g_twr[k]; twi[k] = g_twi[k]; }
    for (int k = tid; k < FBINS; k += 256) {
        float mag0 = __bfloat162float(g_magh[fr0*KPAD + k]) + __bfloat162float(g_magl[fr0*KPAD + k]);
        float mm0 = g_gb[fr0*NGB + k]*mag0 + g_gb[fr0*NGB + FBINS + k];
        sre0[k] = mm0 * g_cosp[fr0*FBINS + k];
        sim0[k] = mm0 * g_sinp[fr0*FBINS + k];
        float mag1 = __bfloat162float(g_magh[fr1*KPAD + k]) + __bfloat162float(g_magl[fr1*KPAD + k]);
        float mm1 = g_gb[fr1*NGB + k]*mag1 + g_gb[fr1*NGB + FBINS + k];
        sre1[k] = mm1 * g_cosp[fr1*FBINS + k];
        sim1[k] = mm1 * g_sinp[fr1*FBINS + k];
    }
    __syncthreads();
    // Z = S0 + i*S1, both Hermitian-extended
    for (int n = tid; n < NFFT; n += 256) {
        float zr, zi;
        if (n <= 512) { zr = sre0[n] - sim1[n];         zi = sim0[n] + sre1[n]; }
        else { int m = NFFT - n; zr = sre0[m] + sim1[m]; zi = sre1[m] - sim0[m]; }
        int j = __brev((unsigned)n) >> 22;
        sr[j] = zr; si[j] = zi;
    }
    __syncthreads();
    for (int s = 1; s <= 10; s++) {
        int half = 1 << (s-1);
        for (int t = tid; t < 512; t += 256) {
            int pos = t & (half-1);
            int grp = t >> (s-1);
            int i1 = (grp << s) + pos;
            int i2 = i1 + half;
            int ti_ = pos << (10 - s);
            float wr = twr[ti_], wi = -twi[ti_];   // conj: inverse
            float xr = sr[i2], xi = si[i2];
            float tr = wr*xr - wi*xi;
            float tq = wr*xi + wi*xr;
            sr[i2] = sr[i1] - tr; si[i2] = si[i1] - tq;
            sr[i1] += tr;         si[i1] += tq;
        }
        __syncthreads();
    }
    const float invn = 1.f/(float)NFFT;
    for (int n = tid; n < NFFT; n += 256) {
        float w = invn*g_win[n];
        g_y[fr0*NFFT + n] = sr[n]*w;
        g_y[fr1*NFFT + n] = si[n]*w;
    }
}

// ---------------- overlap-add ----------------
__global__ void k_overlap(float* __restrict__ out) {
    const int t = blockIdx.x*blockDim.x + threadIdx.x;
    const int b = blockIdx.y;
    if (t >= TSZ) return;
    int ci_hi = t / STRIDE; if (ci_hi > NCH-1) ci_hi = NCH-1;
    int v = t - (CHUNK - 1);
    int ci_lo = (v <= 0) ? 0 : (v + STRIDE - 1)/STRIDE;
    float acc = 0.f;
    for (int ci = ci_lo; ci <= ci_hi; ci++) {
        int n = t - ci*STRIDE;
        int fi_hi = n >> 8; if (fi_hi > NF-1) fi_hi = NF-1;
        int w = n - (NFFT - 1);
        int fi_lo = (w <= 0) ? 0 : (w + HOP - 1) >> 8;
        float s = 0.f;
        for (int fi = fi_lo; fi <= fi_hi; fi++)
            s += g_y[(((b*NCH + ci)*NF) + fi)*NFFT + n - fi*HOP];
        acc += s / fmaxf(g_wsum[n], 1e-8f);
    }
    out[b*TSZ + t] = acc;
}

// ---------------- launch ----------------
extern "C" void kernel_launch(void* const* d_in, const int* in_sizes, int n_in,
                              void* d_out, int out_size) {
    const float* audio     = (const float*)d_in[0];
    const float* emb_table = (const float*)d_in[1];
    const float* gru_wx    = (const float*)d_in[2];
    const float* gru_wh    = (const float*)d_in[3];
    const float* gru_b     = (const float*)d_in[4];
    const float* proj_w    = (const float*)d_in[5];
    const float* proj_b    = (const float*)d_in[6];
    const int*   effect_id = (const int*)  d_in[7];
    float* out = (float*)d_out;

    k_tables<<<(CHUNK + 255)/256, 256>>>();                                   // 1
    k_prep_w<<<(NWX + NPW + 255)/256, 256>>>(gru_wx, proj_w);                 // 2
    k_prep_e<<<BATCH, 256>>>(emb_table, gru_wx, effect_id);                   // 3
    k_fwdfft<<<ROWS/2, 256>>>(audio);                                         // 4 <- profiled
    k_xg<<<dim3(N3H/128, (ROWS + 127)/128), 256, SMEM_GEMM_BYTES>>>();        // 5
    for (int t = 0; t < NF; t++)
        k_gru<<<dim3(HDIM/64, (SEQ + 31)/32), 256>>>(gru_wh, gru_b, t);
    k_proj<<<dim3(PWLD/128, (ROWS + 127)/128), 256, SMEM_GEMM_BYTES>>>(proj_b);
    k_modinv<<<ROWS/2, 256>>>();
    k_overlap<<<dim3((TSZ + 255)/256, BATCH), 256>>>(out);
}

// round 7
// speedup vs baseline: 1.9382x; 1.3760x over previous
#include <cuda_runtime.h>
#include <cuda_bf16.h>
#include <math.h>

// ---------------- problem constants ----------------
#define TSZ    480000
#define BATCH  8
#define CHUNK  4096
#define STRIDE 3072
#define NCH    157
#define NF     13
#define NFFT   1024
#define HOP    256
#define FBINS  513
#define HDIM   256
#define EDIM   128
#define N3H    768
#define SEQ    (BATCH*NCH)   // 1256
#define ROWS   (SEQ*NF)      // 16328
#define CPB    (NCH*NF)      // 2041
#define KPAD   528
#define PWLD   1152
#define NGB    1026
#define PI_F   3.14159265358979323846f

// ---------------- scratch ----------------
__device__ __nv_bfloat16 g_magh[ROWS*KPAD], g_magl[ROWS*KPAD];
__device__ float g_cosp[ROWS*FBINS];
__device__ float g_sinp[ROWS*FBINS];
__device__ float g_xg  [ROWS*N3H];
__device__ float g_hs  [ROWS*HDIM];
__device__ __nv_bfloat16 g_hsh[ROWS*HDIM], g_hsl[ROWS*HDIM];
__device__ float g_gb  [ROWS*NGB];
__device__ float g_y   [ROWS*NFFT];
__device__ float g_embrow[BATCH*N3H];
__device__ float g_wsum[CHUNK];
__device__ __nv_bfloat16 g_wxh[N3H*KPAD], g_wxl[N3H*KPAD];   // [n][k]
__device__ __nv_bfloat16 g_pwh[PWLD*HDIM], g_pwl[PWLD*HDIM]; // [n][k]
__device__ __nv_bfloat16 g_whh[4*192*HDIM], g_whl[4*192*HDIM]; // rearranged [g][gate*64+cc][k]
__device__ float g_twr[512], g_twi[512];
__device__ float g_win[NFFT];

__device__ __forceinline__ float sigf(float x) { return 1.f/(1.f + expf(-x)); }

__device__ __forceinline__ void bsplit(float v, __nv_bfloat16& h, __nv_bfloat16& l) {
    h = __float2bfloat16(v);
    l = __float2bfloat16(v - __bfloat162float(h));
}

__device__ __forceinline__ void mmab(float* c, const unsigned* a, unsigned b0, unsigned b1) {
    asm volatile("mma.sync.aligned.m16n8k16.row.col.f32.bf16.bf16.f32 "
        "{%0,%1,%2,%3}, {%4,%5,%6,%7}, {%8,%9}, {%0,%1,%2,%3};"
        : "+f"(c[0]), "+f"(c[1]), "+f"(c[2]), "+f"(c[3])
        : "r"(a[0]), "r"(a[1]), "r"(a[2]), "r"(a[3]), "r"(b0), "r"(b1));
}
__device__ __forceinline__ void cpa16(unsigned d, const void* s, int sz) {
    asm volatile("cp.async.ca.shared.global [%0], [%1], 16, %2;" :: "r"(d), "l"(s), "r"(sz));
}
#define CPA_COMMIT() asm volatile("cp.async.commit_group;")
#define CPA_WAIT()   asm volatile("cp.async.wait_all;" ::: "memory")

// ---------------- merged prep ----------------
#define PB_TAB 16
#define PB_WX  1584   // N3H*KPAD/256
#define PB_PW  1152   // PWLD*HDIM/256
#define PB_WH  768    // 4*192*256/256
#define NWX (N3H*KPAD)
#define NPW (PWLD*HDIM)
__global__ void k_prep(const float* __restrict__ wx,
                       const float* __restrict__ pw,
                       const float* __restrict__ wh,
                       const float* __restrict__ emb_table,
                       const int*   __restrict__ effect_id) {
    __shared__ float se[EDIM];
    const int bx = blockIdx.x, tid = threadIdx.x;
    if (bx < PB_TAB) {
        int i = bx*256 + tid;
        if (i < 512) {
            float s, c; sincosf(-(2.f*PI_F/NFFT)*i, &s, &c);
            g_twr[i] = c; g_twi[i] = s;
        }
        if (i < NFFT)
            g_win[i] = 0.5f - 0.5f*cosf((2.f*PI_F/NFFT)*i);
        if (i < CHUNK) {
            float ws = 0.f;
            for (int fi = 0; fi < NF; fi++) {
                int d = i - fi*HOP;
                if (d >= 0 && d < NFFT) {
                    float w = 0.5f - 0.5f*cosf((2.f*PI_F/NFFT)*d);
                    ws += w*w;
                }
            }
            g_wsum[i] = ws;
        }
    } else if (bx < PB_TAB + PB_WX) {
        int i = (bx - PB_TAB)*256 + tid;
        int n = i / KPAD, k = i % KPAD;
        float v = (k < FBINS) ? wx[(size_t)k*N3H + n] : 0.f;
        bsplit(v, g_wxh[i], g_wxl[i]);
    } else if (bx < PB_TAB + PB_WX + PB_PW) {
        int j = (bx - PB_TAB - PB_WX)*256 + tid;
        int n = j / HDIM, k = j % HDIM;
        float v = (n < NGB) ? pw[(size_t)k*NGB + n] : 0.f;
        bsplit(v, g_pwh[j], g_pwl[j]);
    } else if (bx < PB_TAB + PB_WX + PB_PW + PB_WH) {
        int j = (bx - PB_TAB - PB_WX - PB_PW)*256 + tid;
        int g = j / 49152, rem = j % 49152;
        int r = rem >> 8, k = rem & 255;
        int gate = r >> 6, cc = r & 63;
        float v = wh[(size_t)k*N3H + gate*256 + g*64 + cc];
        bsplit(v, g_whh[j], g_whl[j]);
    } else {
        int b = bx - PB_TAB - PB_WX - PB_PW - PB_WH;   // 0..7
        if (tid < EDIM) se[tid] = emb_table[effect_id[b]*EDIM + tid];
        __syncthreads();
        for (int j = tid; j < N3H; j += 256) {
            float acc = 0.f;
            #pragma unroll 8
            for (int k = 0; k < EDIM; k++)
                acc += se[k] * wx[(size_t)(FBINS + k)*N3H + j];
            g_embrow[b*N3H + j] = acc;
        }
    }
}

// ---------------- forward STFT: 2 real frames per complex FFT, radix-4 core ----------------
__global__ void k_fwdfft(const float* __restrict__ audio) {
    __shared__ float sr[NFFT], si[NFFT];
    __shared__ float twr[512], twi[512];
    const int pr  = blockIdx.x;
    const int tid = threadIdx.x;
    const int fr0 = 2*pr, fr1 = fr0 + 1;
    const int b0 = fr0 / CPB, r0 = fr0 % CPB;
    const int b1 = fr1 / CPB, r1 = fr1 % CPB;
    const int base0 = (r0/NF)*STRIDE + (r0%NF)*HOP;
    const int base1 = (r1/NF)*STRIDE + (r1%NF)*HOP;

    for (int k = tid; k < 512; k += 256) { twr[k] = g_twr[k]; twi[k] = g_twi[k]; }
    for (int n = tid; n < NFFT; n += 256) {
        int s0 = base0 + n, s1 = base1 + n;
        float v0 = (s0 < TSZ) ? audio[b0*TSZ + s0] : 0.f;
        float v1 = (s1 < TSZ) ? audio[b1*TSZ + s1] : 0.f;
        float w = g_win[n];
        int j = __brev((unsigned)n) >> 22;
        sr[j] = v0*w; si[j] = v1*w;
    }
    __syncthreads();
    // radix-4 (fused radix-2 pairs): stages s = 1,3,5,7,9
    #pragma unroll
    for (int s = 1; s <= 9; s += 2) {
        const int h = 1 << (s-1);
        const int pos = tid & (h-1);
        const int grl = tid >> (s-1);
        const int base = (grl << (s+1)) + pos;
        const float wr1 = twr[pos << (10-s)], wi1 = twi[pos << (10-s)];
        const float wr2 = twr[pos << (9-s)],  wi2 = twi[pos << (9-s)];
        const int e3 = (pos + h) << (9-s);
        const float wr3 = twr[e3], wi3 = twi[e3];
        float x0r = sr[base],       x0i = si[base];
        float x1r = sr[base+h],     x1i = si[base+h];
        float x2r = sr[base+2*h],   x2i = si[base+2*h];
        float x3r = sr[base+3*h],   x3i = si[base+3*h];
        float t1r = wr1*x1r - wi1*x1i, t1i = wr1*x1i + wi1*x1r;
        float u0r = x0r + t1r, u0i = x0i + t1i;
        float u1r = x0r - t1r, u1i = x0i - t1i;
        float t3r = wr1*x3r - wi1*x3i, t3i = wr1*x3i + wi1*x3r;
        float u2r = x2r + t3r, u2i = x2i + t3i;
        float u3r = x2r - t3r, u3i = x2i - t3i;
        float v2r = wr2*u2r - wi2*u2i, v2i = wr2*u2i + wi2*u2r;
        float v3r = wr3*u3r - wi3*u3i, v3i = wr3*u3i + wi3*u3r;
        sr[base]       = u0r + v2r; si[base]       = u0i + v2i;
        sr[base+2*h]   = u0r - v2r; si[base+2*h]   = u0i - v2i;
        sr[base+h]     = u1r + v3r; si[base+h]     = u1i + v3i;
        sr[base+3*h]   = u1r - v3r; si[base+3*h]   = u1i - v3i;
        __syncthreads();
    }
    // Unpack two real spectra via Hermitian symmetry
    for (int k = tid; k < KPAD; k += 256) {
        if (k < FBINS) {
            int m = (NFFT - k) & (NFFT-1);
            float rek = sr[k], imk = si[k];
            float rem = sr[m], imm = si[m];
            float re0 = 0.5f*(rek + rem), i0 = 0.5f*(imk - imm);
            float re1 = 0.5f*(imk + imm), i1 = 0.5f*(rem - rek);
            float mag0 = sqrtf(re0*re0 + i0*i0);
            float c0, s0;
            if (mag0 > 1e-30f) { float inv = 1.f/mag0; c0 = re0*inv; s0 = i0*inv; }
            else               { c0 = 1.f; s0 = 0.f; }
            float mag1 = sqrtf(re1*re1 + i1*i1);
            float c1, s1;
            if (mag1 > 1e-30f) { float inv = 1.f/mag1; c1 = re1*inv; s1 = i1*inv; }
            else               { c1 = 1.f; s1 = 0.f; }
            bsplit(mag0, g_magh[fr0*KPAD + k], g_magl[fr0*KPAD + k]);
            bsplit(mag1, g_magh[fr1*KPAD + k], g_magl[fr1*KPAD + k]);
            g_cosp[fr0*FBINS + k] = c0; g_sinp[fr0*FBINS + k] = s0;
            g_cosp[fr1*FBINS + k] = c1; g_sinp[fr1*FBINS + k] = s1;
        } else {
            __nv_bfloat16 z = __float2bfloat16(0.f);
            g_magh[fr0*KPAD + k] = z; g_magl[fr0*KPAD + k] = z;
            g_magh[fr1*KPAD + k] = z; g_magl[fr1*KPAD + k] = z;
        }
    }
}

// ================= bf16-split 3-pass tensor GEMM (validated) =================
#define SM_PLANE (128*12)
#define SM_AH(p,r,c) smem_u[((p)*128 + (r))*12 + (c)]
#define SM_AL(p,r,c) smem_u[SM_PLANE*2 + ((p)*128 + (r))*12 + (c)]
#define SM_BH(p,r,c) smem_u[SM_PLANE*4 + ((p)*128 + (r))*12 + (c)]
#define SM_BL(p,r,c) smem_u[SM_PLANE*6 + ((p)*128 + (r))*12 + (c)]
#define SMEM_GEMM_BYTES (SM_PLANE*8*4)   // 49152

template<int NIT, int KSTRIDE>
__device__ __forceinline__ void gemm_core(
    unsigned* smem_u,
    const __nv_bfloat16* Ah_g, const __nv_bfloat16* Al_g, int a_row_max,
    const __nv_bfloat16* Bh_g, const __nv_bfloat16* Bl_g,
    int m0, int n0, float acc[2][8][4])
{
    const int tid = threadIdx.x;
    const int lane = tid & 31, wid = tid >> 5;
    const int wm = wid >> 1, wn = wid & 1;
    const int grp = lane >> 2, tig = lane & 3;
    const int row = tid >> 1, half = tid & 1;
    const int arow = m0 + row;
    const int asz = (arow < a_row_max) ? 16 : 0;
    const int brow = n0 + row;

    unsigned sbase = (unsigned)__cvta_generic_to_shared(smem_u);
    unsigned off = (row*12 + half*4)*4;
    unsigned dAh = sbase + off;
    unsigned dAl = sbase + SM_PLANE*2*4 + off;
    unsigned dBh = sbase + SM_PLANE*4*4 + off;
    unsigned dBl = sbase + SM_PLANE*6*4 + off;
    const unsigned bufB = 128*12*4;

    cpa16(dAh, Ah_g + (size_t)arow*KSTRIDE + half*8, asz);
    cpa16(dAl, Al_g + (size_t)arow*KSTRIDE + half*8, asz);
    cpa16(dBh, Bh_g + (size_t)brow*KSTRIDE + half*8, 16);
    cpa16(dBl, Bl_g + (size_t)brow*KSTRIDE + half*8, 16);
    CPA_COMMIT();
    CPA_WAIT();
    __syncthreads();

    #pragma unroll 1
    for (int it = 0; it < NIT; it++) {
        int p = it & 1, q = p ^ 1;
        if (it + 1 < NIT) {
            int k0 = (it+1)*16;
            cpa16(dAh + q*bufB, Ah_g + (size_t)arow*KSTRIDE + k0 + half*8, asz);
            cpa16(dAl + q*bufB, Al_g + (size_t)arow*KSTRIDE + k0 + half*8, asz);
            cpa16(dBh + q*bufB, Bh_g + (size_t)brow*KSTRIDE + k0 + half*8, 16);
            cpa16(dBl + q*bufB, Bl_g + (size_t)brow*KSTRIDE + k0 + half*8, 16);
            CPA_COMMIT();
        }
        unsigned afh[2][4], afl[2][4];
        #pragma unroll
        for (int mt = 0; mt < 2; mt++) {
            int rA = wm*32 + mt*16 + grp;
            afh[mt][0] = SM_AH(p, rA,   tig);
            afh[mt][1] = SM_AH(p, rA+8, tig);
            afh[mt][2] = SM_AH(p, rA,   tig+4);
            afh[mt][3] = SM_AH(p, rA+8, tig+4);
            afl[mt][0] = SM_AL(p, rA,   tig);
            afl[mt][1] = SM_AL(p, rA+8, tig);
            afl[mt][2] = SM_AL(p, rA,   tig+4);
            afl[mt][3] = SM_AL(p, rA+8, tig+4);
        }
        #pragma unroll
        for (int nt = 0; nt < 8; nt++) {
            int cB = wn*64 + nt*8 + grp;
            unsigned bh0 = SM_BH(p, cB, tig);
            unsigned bh1 = SM_BH(p, cB, tig+4);
            unsigned bl0 = SM_BL(p, cB, tig);
            unsigned bl1 = SM_BL(p, cB, tig+4);
            #pragma unroll
            for (int mt = 0; mt < 2; mt++) {
                mmab(acc[mt][nt], afh[mt], bh0, bh1);
                mmab(acc[mt][nt], afh[mt], bl0, bl1);
                mmab(acc[mt][nt], afl[mt], bh0, bh1);
            }
        }
        if (it + 1 < NIT) CPA_WAIT();
        __syncthreads();
    }
}

// ---- k_xg ----
__global__ __launch_bounds__(256, 2) void k_xg() {
    extern __shared__ unsigned smem_u[];
    const int tid = threadIdx.x;
    const int lane = tid & 31, wid = tid >> 5;
    const int wm = wid >> 1, wn = wid & 1;
    const int grp = lane >> 2, tig = lane & 3;
    const int m0 = blockIdx.y * 128, n0 = blockIdx.x * 128;
    float acc[2][8][4] = {};
    gemm_core<33, KPAD>(smem_u, g_magh, g_magl, ROWS, g_wxh, g_wxl, m0, n0, acc);
    #pragma unroll
    for (int mt = 0; mt < 2; mt++) {
        #pragma unroll
        for (int nt = 0; nt < 8; nt++) {
            int row0 = m0 + wm*32 + mt*16 + grp;
            int col0 = n0 + wn*64 + nt*8 + 2*tig;
            if (row0 < ROWS) {
                int b = row0 / CPB;
                g_xg[(size_t)row0*N3H + col0  ] = acc[mt][nt][0] + g_embrow[b*N3H + col0  ];
                g_xg[(size_t)row0*N3H + col0+1] = acc[mt][nt][1] + g_embrow[b*N3H + col0+1];
            }
            int row1 = row0 + 8;
            if (row1 < ROWS) {
                int b = row1 / CPB;
                g_xg[(size_t)row1*N3H + col0  ] = acc[mt][nt][2] + g_embrow[b*N3H + col0  ];
                g_xg[(size_t)row1*N3H + col0+1] = acc[mt][nt][3] + g_embrow[b*N3H + col0+1];
            }
        }
    }
}

// ---- k_proj ----
__global__ __launch_bounds__(256, 2) void k_proj(const float* __restrict__ pb) {
    extern __shared__ unsigned smem_u[];
    const int tid = threadIdx.x;
    const int lane = tid & 31, wid = tid >> 5;
    const int wm = wid >> 1, wn = wid & 1;
    const int grp = lane >> 2, tig = lane & 3;
    const int m0 = blockIdx.y * 128, n0 = blockIdx.x * 128;
    float acc[2][8][4] = {};
    gemm_core<16, HDIM>(smem_u, g_hsh, g_hsl, ROWS, g_pwh, g_pwl, m0, n0, acc);
    #pragma unroll
    for (int mt = 0; mt < 2; mt++) {
        #pragma unroll
        for (int nt = 0; nt < 8; nt++) {
            int row0 = m0 + wm*32 + mt*16 + grp;
            int col0 = n0 + wn*64 + nt*8 + 2*tig;
            if (row0 < ROWS) {
                if (col0   < NGB) g_gb[(size_t)row0*NGB + col0  ] = acc[mt][nt][0] + pb[col0  ];
                if (col0+1 < NGB) g_gb[(size_t)row0*NGB + col0+1] = acc[mt][nt][1] + pb[col0+1];
            }
            int row1 = row0 + 8;
            if (row1 < ROWS) {
                if (col0   < NGB) g_gb[(size_t)row1*NGB + col0  ] = acc[mt][nt][2] + pb[col0  ];
                if (col0+1 < NGB) g_gb[(size_t)row1*NGB + col0+1] = acc[mt][nt][3] + pb[col0+1];
            }
        }
    }
}

// ================= tensor-core GRU step =================
// block: 32 seqs x 192 cols (3 gates x 64 hidden cols of group g). grid (4, 40).
// smem layout (uints): AH [2][32][12] @0, AL @768, BH [2][192][12] @1536, BL @6144.
// After GEMM: hg floats [32][196] alias @0.
#define GRU_SMEM_BYTES (10752*4)   // 43008

__device__ __forceinline__ void gru_load(unsigned sbase, int q, int k0,
                                         int sq0, int g, int t) {
    #pragma unroll
    for (int v = 0; v < 4; v++) {
        int slot = threadIdx.x + v*256;
        if (slot >= 896) break;
        if (slot < 128) {
            int plane = slot >> 6; int s2 = slot & 63;
            int row = s2 >> 1, half = s2 & 1;
            int sq = sq0 + row;
            int prow = sq*NF + t - 1; if (prow < 0) prow = 0;
            int sz = (t > 0 && sq < SEQ) ? 16 : 0;
            const __nv_bfloat16* src = (plane ? g_hsl : g_hsh) + (size_t)prow*HDIM + k0 + half*8;
            unsigned dst = sbase + ((plane ? 768u : 0u) + (q*32 + row)*12 + half*4)*4;
            cpa16(dst, src, sz);
        } else {
            int s2 = slot - 128;
            int plane = (s2 >= 384) ? 1 : 0; if (plane) s2 -= 384;
            int row = s2 >> 1, half = s2 & 1;
            const __nv_bfloat16* src = (plane ? g_whl : g_whh) + (size_t)(g*192 + row)*HDIM + k0 + half*8;
            unsigned dst = sbase + ((plane ? 6144u : 1536u) + (q*192 + row)*12 + half*4)*4;
            cpa16(dst, src, 16);
        }
    }
}

__global__ __launch_bounds__(256, 2) void k_gru(const float* __restrict__ gbias, int t) {
    extern __shared__ unsigned su[];
    const int tid = threadIdx.x;
    const int lane = tid & 31, wid = tid >> 5;
    const int wm = wid >> 2, wn = wid & 3;      // 2 x 4 warps: 16 rows x 48 cols
    const int grp = lane >> 2, tig = lane & 3;
    const int g = blockIdx.x;                   // 0..3
    const int sq0 = blockIdx.y * 32;
    unsigned sbase = (unsigned)__cvta_generic_to_shared(su);

    float acc[6][4] = {};
    gru_load(sbase, 0, 0, sq0, g, t);
    CPA_COMMIT(); CPA_WAIT(); __syncthreads();
    #pragma unroll 1
    for (int it = 0; it < 16; it++) {
        int p = it & 1, q = p ^ 1;
        if (it + 1 < 16) { gru_load(sbase, q, (it+1)*16, sq0, g, t); CPA_COMMIT(); }
        unsigned afh[4], afl[4];
        int rA = wm*16 + grp;
        afh[0] = su[(p*32 + rA)*12 + tig];
        afh[1] = su[(p*32 + rA + 8)*12 + tig];
        afh[2] = su[(p*32 + rA)*12 + tig + 4];
        afh[3] = su[(p*32 + rA + 8)*12 + tig + 4];
        afl[0] = su[768 + (p*32 + rA)*12 + tig];
        afl[1] = su[768 + (p*32 + rA + 8)*12 + tig];
        afl[2] = su[768 + (p*32 + rA)*12 + tig + 4];
        afl[3] = su[768 + (p*32 + rA + 8)*12 + tig + 4];
        #pragma unroll
        for (int nt = 0; nt < 6; nt++) {
            int cB = wn*48 + nt*8 + grp;
            unsigned bh0 = su[1536 + (p*192 + cB)*12 + tig];
            unsigned bh1 = su[1536 + (p*192 + cB)*12 + tig + 4];
            unsigned bl0 = su[6144 + (p*192 + cB)*12 + tig];
            unsigned bl1 = su[6144 + (p*192 + cB)*12 + tig + 4];
            mmab(acc[nt], afh, bh0, bh1);
            mmab(acc[nt], afh, bl0, bl1);
            mmab(acc[nt], afl, bh0, bh1);
        }
        if (it + 1 < 16) CPA_WAIT();
        __syncthreads();
    }
    // stage hg to smem (aliases GEMM smem; all mma reads done after final sync)
    float* hg = (float*)su;
    #pragma unroll
    for (int nt = 0; nt < 6; nt++) {
        int r0 = wm*16 + grp, c0 = wn*48 + nt*8 + 2*tig;
        hg[r0*196 + c0]         = acc[nt][0];
        hg[r0*196 + c0 + 1]     = acc[nt][1];
        hg[(r0+8)*196 + c0]     = acc[nt][2];
        hg[(r0+8)*196 + c0 + 1] = acc[nt][3];
    }
    __syncthreads();
    // fused gates: 32 seqs x 64 hidden cols
    for (int e = tid; e < 32*64; e += 256) {
        int s = e >> 6, cc = e & 63;
        int sq = sq0 + s;
        if (sq >= SEQ) continue;
        int c = g*64 + cc;
        const float* xg = &g_xg[(size_t)(sq*NF + t)*N3H];
        float z = sigf(xg[c]           + hg[s*196 + cc]        + gbias[c]);
        float r = sigf(xg[HDIM + c]    + hg[s*196 + 64 + cc]   + gbias[HDIM + c]);
        float n = tanhf(xg[2*HDIM + c] + r*(hg[s*196 + 128 + cc] + gbias[2*HDIM + c]));
        float hp = 0.f;
        if (t > 0) hp = g_hs[(size_t)(sq*NF + t - 1)*HDIM + c];
        float h = (1.f - z)*n + z*hp;
        size_t hi = (size_t)(sq*NF + t)*HDIM + c;
        g_hs[hi] = h;
        bsplit(h, g_hsh[hi], g_hsl[hi]);
    }
}

// ---------------- modulate + inverse FFT (radix-4 core, 2 frames/block) ----------------
__global__ void k_modinv() {
    __shared__ float sre0[FBINS], sim0[FBINS], sre1[FBINS], sim1[FBINS];
    __shared__ float sr[NFFT], si[NFFT];
    __shared__ float twr[512], twi[512];
    const int pr  = blockIdx.x;
    const int tid = threadIdx.x;
    const int fr0 = 2*pr, fr1 = fr0 + 1;

    for (int k = tid; k < 512; k += 256) { twr[k] = g_twr[k]; twi[k] = g_twi[k]; }
    for (int k = tid; k < FBINS; k += 256) {
        float mag0 = __bfloat162float(g_magh[fr0*KPAD + k]) + __bfloat162float(g_magl[fr0*KPAD + k]);
        float mm0 = g_gb[(size_t)fr0*NGB + k]*mag0 + g_gb[(size_t)fr0*NGB + FBINS + k];
        sre0[k] = mm0 * g_cosp[fr0*FBINS + k];
        sim0[k] = mm0 * g_sinp[fr0*FBINS + k];
        float mag1 = __bfloat162float(g_magh[fr1*KPAD + k]) + __bfloat162float(g_magl[fr1*KPAD + k]);
        float mm1 = g_gb[(size_t)fr1*NGB + k]*mag1 + g_gb[(size_t)fr1*NGB + FBINS + k];
        sre1[k] = mm1 * g_cosp[fr1*FBINS + k];
        sim1[k] = mm1 * g_sinp[fr1*FBINS + k];
    }
    __syncthreads();
    for (int n = tid; n < NFFT; n += 256) {
        float zr, zi;
        if (n <= 512) { zr = sre0[n] - sim1[n];         zi = sim0[n] + sre1[n]; }
        else { int m = NFFT - n; zr = sre0[m] + sim1[m]; zi = sre1[m] - sim0[m]; }
        int j = __brev((unsigned)n) >> 22;
        sr[j] = zr; si[j] = zi;
    }
    __syncthreads();
    #pragma unroll
    for (int s = 1; s <= 9; s += 2) {
        const int h = 1 << (s-1);
        const int pos = tid & (h-1);
        const int grl = tid >> (s-1);
        const int base = (grl << (s+1)) + pos;
        const float wr1 = twr[pos << (10-s)], wi1 = -twi[pos << (10-s)];
        const float wr2 = twr[pos << (9-s)],  wi2 = -twi[pos << (9-s)];
        const int e3 = (pos + h) << (9-s);
        const float wr3 = twr[e3], wi3 = -twi[e3];
        float x0r = sr[base],       x0i = si[base];
        float x1r = sr[base+h],     x1i = si[base+h];
        float x2r = sr[base+2*h],   x2i = si[base+2*h];
        float x3r = sr[base+3*h],   x3i = si[base+3*h];
        float t1r = wr1*x1r - wi1*x1i, t1i = wr1*x1i + wi1*x1r;
        float u0r = x0r + t1r, u0i = x0i + t1i;
        float u1r = x0r - t1r, u1i = x0i - t1i;
        float t3r = wr1*x3r - wi1*x3i, t3i = wr1*x3i + wi1*x3r;
        float u2r = x2r + t3r, u2i = x2i + t3i;
        float u3r = x2r - t3r, u3i = x2i - t3i;
        float v2r = wr2*u2r - wi2*u2i, v2i = wr2*u2i + wi2*u2r;
        float v3r = wr3*u3r - wi3*u3i, v3i = wr3*u3i + wi3*u3r;
        sr[base]       = u0r + v2r; si[base]       = u0i + v2i;
        sr[base+2*h]   = u0r - v2r; si[base+2*h]   = u0i - v2i;
        sr[base+h]     = u1r + v3r; si[base+h]     = u1i + v3i;
        sr[base+3*h]   = u1r - v3r; si[base+3*h]   = u1i - v3i;
        __syncthreads();
    }
    const float invn = 1.f/(float)NFFT;
    for (int n = tid; n < NFFT; n += 256) {
        float w = invn*g_win[n];
        g_y[(size_t)fr0*NFFT + n] = sr[n]*w;
        g_y[(size_t)fr1*NFFT + n] = si[n]*w;
    }
}

// ---------------- overlap-add ----------------
__global__ void k_overlap(float* __restrict__ out) {
    const int t = blockIdx.x*blockDim.x + threadIdx.x;
    const int b = blockIdx.y;
    if (t >= TSZ) return;
    int ci_hi = t / STRIDE; if (ci_hi > NCH-1) ci_hi = NCH-1;
    int v = t - (CHUNK - 1);
    int ci_lo = (v <= 0) ? 0 : (v + STRIDE - 1)/STRIDE;
    float acc = 0.f;
    for (int ci = ci_lo; ci <= ci_hi; ci++) {
        int n = t - ci*STRIDE;
        int fi_hi = n >> 8; if (fi_hi > NF-1) fi_hi = NF-1;
        int w = n - (NFFT - 1);
        int fi_lo = (w <= 0) ? 0 : (w + HOP - 1) >> 8;
        float s = 0.f;
        for (int fi = fi_lo; fi <= fi_hi; fi++)
            s += g_y[(size_t)(((b*NCH + ci)*NF) + fi)*NFFT + n - fi*HOP];
        acc += s / fmaxf(g_wsum[n], 1e-8f);
    }
    out[b*TSZ + t] = acc;
}

// ---------------- launch ----------------
extern "C" void kernel_launch(void* const* d_in, const int* in_sizes, int n_in,
                              void* d_out, int out_size) {
    const float* audio     = (const float*)d_in[0];
    const float* emb_table = (const float*)d_in[1];
    const float* gru_wx    = (const float*)d_in[2];
    const float* gru_wh    = (const float*)d_in[3];
    const float* gru_b     = (const float*)d_in[4];
    const float* proj_w    = (const float*)d_in[5];
    const float* proj_b    = (const float*)d_in[6];
    const int*   effect_id = (const int*)  d_in[7];
    float* out = (float*)d_out;

    k_prep<<<PB_TAB + PB_WX + PB_PW + PB_WH + BATCH, 256>>>(
        gru_wx, proj_w, gru_wh, emb_table, effect_id);                        // 1
    k_fwdfft<<<ROWS/2, 256>>>(audio);                                         // 2
    k_xg<<<dim3(N3H/128, (ROWS + 127)/128), 256, SMEM_GEMM_BYTES>>>();        // 3
    for (int t = 0; t < NF; t++)                                              // 4..16 (slot 4 = t=0, representative)
        k_gru<<<dim3(4, 40), 256, GRU_SMEM_BYTES>>>(gru_b, t);
    k_proj<<<dim3(PWLD/128, (ROWS + 127)/128), 256, SMEM_GEMM_BYTES>>>(proj_b);
    k_modinv<<<ROWS/2, 256>>>();
    k_overlap<<<dim3((TSZ + 255)/256, BATCH), 256>>>(out);
}